// round 3
// baseline (speedup 1.0000x reference)
#include <cuda_runtime.h>

#define FEAT 64

// Scratch ping-pong buffers (static __device__ — no allocation allowed).
// float4 so base is 16B-aligned (vector loads + red.global.add.v4.f32 trap
// on misalignment).
#define NMAX 100000
__device__ float4 g_bufA[(size_t)NMAX * (FEAT / 4)];
__device__ float4 g_bufB[(size_t)NMAX * (FEAT / 4)];

// ---------------------------------------------------------------------------
// copy: agg = h  (the "+h" part of GIN agg = sum_neigh + h)
// ---------------------------------------------------------------------------
__global__ void copy_kernel(float4* __restrict__ dst, const float4* __restrict__ src, int n4) {
    int i = blockIdx.x * blockDim.x + threadIdx.x;
    if (i < n4) dst[i] = src[i];
}

__global__ void zero_kernel(float* __restrict__ p, int n) {
    int i = blockIdx.x * blockDim.x + threadIdx.x;
    if (i < n) p[i] = 0.0f;
}

// ---------------------------------------------------------------------------
// scatter: agg[dst] += h[src]   (16 threads per edge, one float4 each,
// red.global.add.v4.f32 for 16B-granular L2 reductions).
// Indices are int32 (harness narrows int64 inputs to int32).
// ---------------------------------------------------------------------------
__global__ void scatter_kernel(float4* __restrict__ agg, const float4* __restrict__ h4,
                               const int* __restrict__ ei, int E) {
    int tid  = blockIdx.x * blockDim.x + threadIdx.x;
    int lane = threadIdx.x & 31;
    int e    = tid >> 4;            // 16 threads per edge
    int e_cl = min(e, E - 1);
    int s = 0, d = 0;
    if ((lane & 15) == 0) {         // lanes 0 and 16 load the two edges' indices
        s = ei[e_cl];
        d = ei[(size_t)E + e_cl];
    }
    s = __shfl_sync(0xffffffffu, s, lane & 16);
    d = __shfl_sync(0xffffffffu, d, lane & 16);
    int f4 = tid & 15;
    float4 v = h4[(size_t)s * 16 + f4];
    if (e < E) {
        float4* p = agg + (size_t)d * 16 + f4;
        asm volatile("red.global.add.v4.f32 [%0], {%1, %2, %3, %4};"
                     :: "l"(p), "f"(v.x), "f"(v.y), "f"(v.z), "f"(v.w)
                     : "memory");
    }
}

// ---------------------------------------------------------------------------
// fused GEMM + sigmoid:  Y = sigmoid(X @ W),  X:[N,64], W:[64,64]
// 256 threads/block, 32 rows/block, 8 output cols/thread.
// Inner product via packed fma.rn.f32x2 (2 FLOPs/instr — FFMA2 pattern).
// ---------------------------------------------------------------------------
__global__ __launch_bounds__(256) void gemm_sig_kernel(
    float* __restrict__ Y, const float* __restrict__ X,
    const float* __restrict__ W, int Nn)
{
    __shared__ float sW[64 * 64];   // 16 KB
    __shared__ float sX[32 * 64];   // 8 KB
    int tid  = threadIdx.x;
    int row0 = blockIdx.x * 32;

    // stage W
    const float4* W4 = (const float4*)W;
    float4* sW4 = (float4*)sW;
#pragma unroll
    for (int i = 0; i < 4; i++) sW4[tid + 256 * i] = W4[tid + 256 * i];

    // stage X tile (guarded)
    float4* sX4 = (float4*)sX;
#pragma unroll
    for (int i = 0; i < 2; i++) {
        int idx  = tid + 256 * i;         // float4 index within tile
        int lr   = idx >> 4;              // local row
        int f4   = idx & 15;
        int grow = row0 + lr;
        float4 v = make_float4(0.f, 0.f, 0.f, 0.f);
        if (grow < Nn) v = *(const float4*)(X + (size_t)grow * 64 + f4 * 4);
        sX4[idx] = v;
    }
    __syncthreads();

    int r  = tid >> 3;          // 0..31 local row
    int c8 = (tid & 7) << 3;    // output col group start

    unsigned long long acc0 = 0, acc1 = 0, acc2 = 0, acc3 = 0;
    const float* xp = sX + r * 64;
#pragma unroll
    for (int k = 0; k < 64; k++) {
        float xv = xp[k];
        unsigned long long xv2;
        asm("mov.b64 %0, {%1, %1};" : "=l"(xv2) : "f"(xv));
        const float* wp = sW + k * 64 + c8;
        float4 w0 = *(const float4*)wp;
        float4 w1 = *(const float4*)(wp + 4);
        unsigned long long p0, p1, p2, p3;
        asm("mov.b64 %0, {%1, %2};" : "=l"(p0) : "f"(w0.x), "f"(w0.y));
        asm("mov.b64 %0, {%1, %2};" : "=l"(p1) : "f"(w0.z), "f"(w0.w));
        asm("mov.b64 %0, {%1, %2};" : "=l"(p2) : "f"(w1.x), "f"(w1.y));
        asm("mov.b64 %0, {%1, %2};" : "=l"(p3) : "f"(w1.z), "f"(w1.w));
        asm("fma.rn.f32x2 %0, %1, %2, %0;" : "+l"(acc0) : "l"(xv2), "l"(p0));
        asm("fma.rn.f32x2 %0, %1, %2, %0;" : "+l"(acc1) : "l"(xv2), "l"(p1));
        asm("fma.rn.f32x2 %0, %1, %2, %0;" : "+l"(acc2) : "l"(xv2), "l"(p2));
        asm("fma.rn.f32x2 %0, %1, %2, %0;" : "+l"(acc3) : "l"(xv2), "l"(p3));
    }

    int row = row0 + r;
    if (row < Nn) {
        float a[8];
        asm("mov.b64 {%0, %1}, %2;" : "=f"(a[0]), "=f"(a[1]) : "l"(acc0));
        asm("mov.b64 {%0, %1}, %2;" : "=f"(a[2]), "=f"(a[3]) : "l"(acc1));
        asm("mov.b64 {%0, %1}, %2;" : "=f"(a[4]), "=f"(a[5]) : "l"(acc2));
        asm("mov.b64 {%0, %1}, %2;" : "=f"(a[6]), "=f"(a[7]) : "l"(acc3));
        float y[8];
#pragma unroll
        for (int j = 0; j < 8; j++) y[j] = 1.0f / (1.0f + __expf(-a[j]));
        float4 o0 = make_float4(y[0], y[1], y[2], y[3]);
        float4 o1 = make_float4(y[4], y[5], y[6], y[7]);
        *(float4*)(Y + (size_t)row * 64 + c8)     = o0;
        *(float4*)(Y + (size_t)row * 64 + c8 + 4) = o1;
    }
}

// ---------------------------------------------------------------------------
// pool: xr[batch[n]] += h[n]  (16 threads/node, v4 reductions into 32KB target)
// ---------------------------------------------------------------------------
__global__ void pool_kernel(float4* __restrict__ xr, const float4* __restrict__ h,
                            const int* __restrict__ batch, int Nn) {
    int tid  = blockIdx.x * blockDim.x + threadIdx.x;
    int lane = threadIdx.x & 31;
    int n    = tid >> 4;
    int n_cl = min(n, Nn - 1);
    int g = 0;
    if ((lane & 15) == 0) g = batch[n_cl];
    g = __shfl_sync(0xffffffffu, g, lane & 16);
    int f4 = tid & 15;
    float4 v = h[(size_t)n_cl * 16 + f4];
    if (n < Nn) {
        float4* p = xr + (size_t)g * 16 + f4;
        asm volatile("red.global.add.v4.f32 [%0], {%1, %2, %3, %4};"
                     :: "l"(p), "f"(v.x), "f"(v.y), "f"(v.z), "f"(v.w)
                     : "memory");
    }
}

// ---------------------------------------------------------------------------
// head: logits = xr @ fc_w^T + fc_b ; out = log_softmax(logits)
// one thread per graph (B threads total)
// ---------------------------------------------------------------------------
__global__ void head_kernel(float* __restrict__ out, const float* __restrict__ xr,
                            const float* __restrict__ fc_w, const float* __restrict__ fc_b,
                            int C, int B) {
    int g = blockIdx.x * blockDim.x + threadIdx.x;
    if (g >= B) return;
    float xv[FEAT];
#pragma unroll
    for (int i = 0; i < FEAT; i++) xv[i] = xr[(size_t)g * FEAT + i];
    float lg[16];
    float m = -1e30f;
    for (int c = 0; c < C; c++) {
        float s = fc_b[c];
#pragma unroll
        for (int i = 0; i < FEAT; i++) s += xv[i] * fc_w[(size_t)c * FEAT + i];
        lg[c] = s;
        m = fmaxf(m, s);
    }
    float sum = 0.0f;
    for (int c = 0; c < C; c++) sum += expf(lg[c] - m);
    float lse = m + logf(sum);
    for (int c = 0; c < C; c++) out[(size_t)g * C + c] = lg[c] - lse;
}

// ---------------------------------------------------------------------------
extern "C" void kernel_launch(void* const* d_in, const int* in_sizes, int n_in,
                              void* d_out, int out_size) {
    const float* x     = (const float*)d_in[0];
    const int*   ei    = (const int*)d_in[1];    // int64 narrowed to int32 by harness
    const int*   batch = (const int*)d_in[2];    // ditto
    const float* W1s   = (const float*)d_in[3];
    const float* W2s   = (const float*)d_in[4];
    const float* fc_w  = (const float*)d_in[5];
    const float* fc_b  = (const float*)d_in[6];

    int Nn = in_sizes[0] / FEAT;           // 100000
    int E  = in_sizes[1] / 2;              // 1600000
    int C  = in_sizes[6];                  // 10
    int L  = in_sizes[3] / (FEAT * FEAT);  // 4
    int B  = out_size / (C + FEAT);        // 128

    float4 *bufA = nullptr, *bufB = nullptr;
    cudaGetSymbolAddress((void**)&bufA, g_bufA);
    cudaGetSymbolAddress((void**)&bufB, g_bufB);

    int n4         = Nn * 16;                       // float4 count per feature map
    int copyBlocks = (n4 + 255) / 256;
    int scatBlocks = (E * 16 + 255) / 256;
    int gemmBlocks = (Nn + 31) / 32;

    const float4* h = (const float4*)x;
    float4* ba = bufA;
    float4* bb = bufB;
    for (int l = 0; l < L; l++) {
        // agg = h  (copy), then agg += sum of neighbor features
        copy_kernel<<<copyBlocks, 256>>>(ba, h, n4);
        scatter_kernel<<<scatBlocks, 256>>>(ba, h, ei, E);
        // h = sigmoid(sigmoid(agg @ W1) @ W2)
        gemm_sig_kernel<<<gemmBlocks, 256>>>((float*)bb, (const float*)ba,
                                             W1s + (size_t)l * FEAT * FEAT, Nn);
        gemm_sig_kernel<<<gemmBlocks, 256>>>((float*)ba, (const float*)bb,
                                             W2s + (size_t)l * FEAT * FEAT, Nn);
        h = ba;
        float4* t = ba; ba = bb; bb = t;
    }

    float* out = (float*)d_out;
    float* xr  = out + (size_t)B * C;   // second tuple element lives after log_softmax

    zero_kernel<<<(out_size + 255) / 256, 256>>>(out, out_size);
    pool_kernel<<<(Nn * 16 + 255) / 256, 256>>>((float4*)xr, h, batch, Nn);
    head_kernel<<<(B + 127) / 128, 128>>>(out, xr, fc_w, fc_b, C, B);
}

// round 4
// speedup vs baseline: 1.8559x; 1.8559x over previous
#include <cuda_runtime.h>

#define FEAT 64

// Scratch ping-pong buffers, float4 for 16B alignment (v4 RED/LDG.128).
#define NMAX 100000
__device__ float4 g_bufA[(size_t)NMAX * (FEAT / 4)];
__device__ float4 g_bufB[(size_t)NMAX * (FEAT / 4)];

// ---------------------------------------------------------------------------
__global__ void copy_kernel(float4* __restrict__ dst, const float4* __restrict__ src, int n4) {
    int i = blockIdx.x * blockDim.x + threadIdx.x;
    if (i < n4) dst[i] = src[i];
}

__global__ void zero_kernel(float* __restrict__ p, int n) {
    int i = blockIdx.x * blockDim.x + threadIdx.x;
    if (i < n) p[i] = 0.0f;
}

// ---------------------------------------------------------------------------
// scatter: agg[dst] += h[src]  (16 threads/edge, red.global.add.v4.f32)
// ---------------------------------------------------------------------------
__global__ void scatter_kernel(float4* __restrict__ agg, const float4* __restrict__ h4,
                               const int* __restrict__ ei, int E) {
    int tid  = blockIdx.x * blockDim.x + threadIdx.x;
    int lane = threadIdx.x & 31;
    int e    = tid >> 4;
    int e_cl = min(e, E - 1);
    int s = 0, d = 0;
    if ((lane & 15) == 0) {
        s = ei[e_cl];
        d = ei[(size_t)E + e_cl];
    }
    s = __shfl_sync(0xffffffffu, s, lane & 16);
    d = __shfl_sync(0xffffffffu, d, lane & 16);
    int f4 = tid & 15;
    float4 v = h4[(size_t)s * 16 + f4];
    if (e < E) {
        float4* p = agg + (size_t)d * 16 + f4;
        asm volatile("red.global.add.v4.f32 [%0], {%1, %2, %3, %4};"
                     :: "l"(p), "f"(v.x), "f"(v.y), "f"(v.z), "f"(v.w)
                     : "memory");
    }
}

// ---------------------------------------------------------------------------
// Register-blocked fused GEMM + sigmoid: Y = sigmoid(X @ W)
//   128 rows/block, 256 threads: thread = (tr 0..15) x (tc 0..15)
//   each thread: 8 rows x 4 cols, FMA2 paired over (k, k+1)
//   sWT: W transposed [col][k], stride 66 + bank skew; sX: [row][k], stride 66
//   If Y2 != null, result is also stored there (folds the agg=h copy).
// ---------------------------------------------------------------------------
#define SXS 66
#define SWS 66
#define SW_FLOATS 4240            // 63*66 + 6 + 63 = 4227, padded even
#define SX_FLOATS 8448            // 127*66 + 63 = 8445, padded
#define GEMM_SMEM_BYTES ((SW_FLOATS + SX_FLOATS) * 4)

__global__ __launch_bounds__(256, 2) void gemm_sig_kernel(
    float* __restrict__ Y, float* __restrict__ Y2,
    const float* __restrict__ X, const float* __restrict__ W, int Nn)
{
    extern __shared__ float sm[];
    float* sWT = sm;               // [64 cols][stride 66 + skew]
    float* sX  = sm + SW_FLOATS;   // [128 rows][stride 66]
    int tid  = threadIdx.x;
    int row0 = blockIdx.x * 128;

    // stage W transposed with per-16-col skew: col c at c*66 + ((c>>4)&3)*2
    const float4* W4 = (const float4*)W;
#pragma unroll
    for (int it = 0; it < 4; it++) {
        int idx = tid + it * 256;      // 0..1023
        int k   = idx >> 4;            // 0..63
        int c4  = idx & 15;
        float4 v = W4[idx];            // W[k][c4*4 .. c4*4+3]
        int c = c4 * 4;
        sWT[(c + 0) * SWS + (((c + 0) >> 4) & 3) * 2 + k] = v.x;
        sWT[(c + 1) * SWS + (((c + 1) >> 4) & 3) * 2 + k] = v.y;
        sWT[(c + 2) * SWS + (((c + 2) >> 4) & 3) * 2 + k] = v.z;
        sWT[(c + 3) * SWS + (((c + 3) >> 4) & 3) * 2 + k] = v.w;
    }

    // stage X rows (row-major, stride 66)
    const float4* X4 = (const float4*)X;
#pragma unroll
    for (int it = 0; it < 8; it++) {
        int idx = tid + it * 256;      // 0..2047
        int r   = idx >> 4;            // 0..127
        int k4  = idx & 15;
        int grow = row0 + r;
        float4 v = make_float4(0.f, 0.f, 0.f, 0.f);
        if (grow < Nn) v = X4[(size_t)grow * 16 + k4];
        float* dp = &sX[r * SXS + k4 * 4];
        dp[0] = v.x; dp[1] = v.y; dp[2] = v.z; dp[3] = v.w;
    }
    __syncthreads();

    int tr = tid >> 4;      // 0..15 -> rows tr*8 .. tr*8+7
    int tc = tid & 15;      // 0..15 -> cols tc*4 .. tc*4+3
    const float* xb = sX + tr * 8 * SXS;
    const float* wb = sWT + tc * 4 * SWS + ((tc >> 2) & 3) * 2;  // skew const over c=0..3

    unsigned long long acc[4][8];
#pragma unroll
    for (int c = 0; c < 4; c++)
#pragma unroll
        for (int i = 0; i < 8; i++) acc[c][i] = 0ull;

#pragma unroll 2
    for (int k = 0; k < 64; k += 2) {
        unsigned long long xv[8], wv[4];
#pragma unroll
        for (int i = 0; i < 8; i++)
            xv[i] = *(const unsigned long long*)(xb + i * SXS + k);
#pragma unroll
        for (int c = 0; c < 4; c++)
            wv[c] = *(const unsigned long long*)(wb + c * SWS + k);
#pragma unroll
        for (int i = 0; i < 8; i++)
#pragma unroll
            for (int c = 0; c < 4; c++)
                asm("fma.rn.f32x2 %0, %1, %2, %0;"
                    : "+l"(acc[c][i]) : "l"(xv[i]), "l"(wv[c]));
    }

    int cbase = tc * 4;
#pragma unroll
    for (int i = 0; i < 8; i++) {
        int row = row0 + tr * 8 + i;
        if (row < Nn) {
            float o[4];
#pragma unroll
            for (int c = 0; c < 4; c++) {
                float lo, hi;
                asm("mov.b64 {%0, %1}, %2;" : "=f"(lo), "=f"(hi) : "l"(acc[c][i]));
                float v = lo + hi;
                o[c] = 1.0f / (1.0f + __expf(-v));
            }
            float4 ov = make_float4(o[0], o[1], o[2], o[3]);
            *(float4*)(Y + (size_t)row * 64 + cbase) = ov;
            if (Y2) *(float4*)(Y2 + (size_t)row * 64 + cbase) = ov;
        }
    }
}

// ---------------------------------------------------------------------------
// pool: xr[batch[n]] += h[n]
// ---------------------------------------------------------------------------
__global__ void pool_kernel(float4* __restrict__ xr, const float4* __restrict__ h,
                            const int* __restrict__ batch, int Nn) {
    int tid  = blockIdx.x * blockDim.x + threadIdx.x;
    int lane = threadIdx.x & 31;
    int n    = tid >> 4;
    int n_cl = min(n, Nn - 1);
    int g = 0;
    if ((lane & 15) == 0) g = batch[n_cl];
    g = __shfl_sync(0xffffffffu, g, lane & 16);
    int f4 = tid & 15;
    float4 v = h[(size_t)n_cl * 16 + f4];
    if (n < Nn) {
        float4* p = xr + (size_t)g * 16 + f4;
        asm volatile("red.global.add.v4.f32 [%0], {%1, %2, %3, %4};"
                     :: "l"(p), "f"(v.x), "f"(v.y), "f"(v.z), "f"(v.w)
                     : "memory");
    }
}

// ---------------------------------------------------------------------------
// head: logits = xr @ fc_w^T + fc_b ; out = log_softmax(logits)
// ---------------------------------------------------------------------------
__global__ void head_kernel(float* __restrict__ out, const float* __restrict__ xr,
                            const float* __restrict__ fc_w, const float* __restrict__ fc_b,
                            int C, int B) {
    int g = blockIdx.x * blockDim.x + threadIdx.x;
    if (g >= B) return;
    float xv[FEAT];
#pragma unroll
    for (int i = 0; i < FEAT; i++) xv[i] = xr[(size_t)g * FEAT + i];
    float lg[16];
    float m = -1e30f;
    for (int c = 0; c < C; c++) {
        float s = fc_b[c];
#pragma unroll
        for (int i = 0; i < FEAT; i++) s += xv[i] * fc_w[(size_t)c * FEAT + i];
        lg[c] = s;
        m = fmaxf(m, s);
    }
    float sum = 0.0f;
    for (int c = 0; c < C; c++) sum += expf(lg[c] - m);
    float lse = m + logf(sum);
    for (int c = 0; c < C; c++) out[(size_t)g * C + c] = lg[c] - lse;
}

// ---------------------------------------------------------------------------
extern "C" void kernel_launch(void* const* d_in, const int* in_sizes, int n_in,
                              void* d_out, int out_size) {
    const float* x     = (const float*)d_in[0];
    const int*   ei    = (const int*)d_in[1];    // int64 narrowed to int32 by harness
    const int*   batch = (const int*)d_in[2];
    const float* W1s   = (const float*)d_in[3];
    const float* W2s   = (const float*)d_in[4];
    const float* fc_w  = (const float*)d_in[5];
    const float* fc_b  = (const float*)d_in[6];

    int Nn = in_sizes[0] / FEAT;           // 100000
    int E  = in_sizes[1] / 2;              // 1600000
    int C  = in_sizes[6];                  // 10
    int L  = in_sizes[3] / (FEAT * FEAT);  // 4
    int B  = out_size / (C + FEAT);        // 128

    static int smem_set = 0;
    if (!smem_set) {
        cudaFuncSetAttribute(gemm_sig_kernel,
                             cudaFuncAttributeMaxDynamicSharedMemorySize,
                             GEMM_SMEM_BYTES);
        smem_set = 1;
    }

    float4 *bufA = nullptr, *bufB = nullptr;
    cudaGetSymbolAddress((void**)&bufA, g_bufA);
    cudaGetSymbolAddress((void**)&bufB, g_bufB);
    float* A = (float*)bufA;
    float* Bv = (float*)bufB;

    int n4         = Nn * 16;
    int copyBlocks = (n4 + 255) / 256;
    int scatBlocks = (E * 16 + 255) / 256;
    int gemmBlocks = (Nn + 127) / 128;

    // layer 0 agg init: A = x
    copy_kernel<<<copyBlocks, 256>>>((float4*)A, (const float4*)x, n4);

    for (int l = 0; l < L; l++) {
        const float* h = (l == 0) ? x : Bv;
        // A += sum of neighbor features of h
        scatter_kernel<<<scatBlocks, 256>>>((float4*)A, (const float4*)h, ei, E);
        // A = sigmoid(A @ W1)   (in place: each block stages its rows first)
        gemm_sig_kernel<<<gemmBlocks, 256, GEMM_SMEM_BYTES>>>(
            A, nullptr, A, W1s + (size_t)l * FEAT * FEAT, Nn);
        // B = sigmoid(A @ W2); also A = same (agg init for next layer)
        float* dual = (l < L - 1) ? A : nullptr;
        gemm_sig_kernel<<<gemmBlocks, 256, GEMM_SMEM_BYTES>>>(
            Bv, dual, A, W2s + (size_t)l * FEAT * FEAT, Nn);
    }

    float* out = (float*)d_out;
    float* xr  = out + (size_t)B * C;

    zero_kernel<<<(out_size + 255) / 256, 256>>>(out, out_size);
    pool_kernel<<<(Nn * 16 + 255) / 256, 256>>>((float4*)xr, (const float4*)Bv, batch, Nn);
    head_kernel<<<(B + 127) / 128, 128>>>(out, xr, fc_w, fc_b, C, B);
}

// round 5
// speedup vs baseline: 2.1781x; 1.1736x over previous
#include <cuda_runtime.h>

#define FEAT 64

// Scratch buffers (static __device__ — no allocation allowed).
#define NMAX 100000
#define EMAX 1600000
__device__ float4 g_bufA[(size_t)NMAX * (FEAT / 4)];
__device__ float4 g_bufB[(size_t)NMAX * (FEAT / 4)];
__device__ int    g_rowptr[NMAX + 1];
__device__ int    g_cursor[NMAX];      // doubles as degree histogram
__device__ int    g_adj[EMAX];
__device__ int    g_bsum[1024];

// ---------------------------------------------------------------------------
__global__ void zero_kernel(float* __restrict__ p, int n) {
    int i = blockIdx.x * blockDim.x + threadIdx.x;
    if (i < n) p[i] = 0.0f;
}
__global__ void zero_int_kernel(int* __restrict__ p, int n) {
    int i = blockIdx.x * blockDim.x + threadIdx.x;
    if (i < n) p[i] = 0;
}

// ---------------------------------------------------------------------------
// CSR build: histogram -> scan -> fill
// ---------------------------------------------------------------------------
__global__ void hist_kernel(int* __restrict__ deg, const int* __restrict__ ei, int E) {
    int e = blockIdx.x * blockDim.x + threadIdx.x;
    if (e < E) atomicAdd(&deg[ei[(size_t)E + e]], 1);   // dst histogram
}

// per-block exclusive scan of deg -> rowptr; block totals -> bsum
__global__ void scan1_kernel(const int* __restrict__ deg, int* __restrict__ rowptr,
                             int* __restrict__ bsum, int Nn) {
    __shared__ int sm[256];
    int i = blockIdx.x * 256 + threadIdx.x;
    int v = (i < Nn) ? deg[i] : 0;
    sm[threadIdx.x] = v;
    __syncthreads();
    for (int off = 1; off < 256; off <<= 1) {
        int t = (threadIdx.x >= off) ? sm[threadIdx.x - off] : 0;
        __syncthreads();
        sm[threadIdx.x] += t;
        __syncthreads();
    }
    if (i < Nn) rowptr[i] = sm[threadIdx.x] - v;       // block-local exclusive
    if (threadIdx.x == 255) bsum[blockIdx.x] = sm[255];
}

// single-block exclusive scan of block sums (nb <= 512)
__global__ void scan2_kernel(int* __restrict__ bsum, int nb) {
    __shared__ int sm[512];
    int v = (threadIdx.x < nb) ? bsum[threadIdx.x] : 0;
    sm[threadIdx.x] = v;
    __syncthreads();
    for (int off = 1; off < 512; off <<= 1) {
        int t = (threadIdx.x >= off) ? sm[threadIdx.x - off] : 0;
        __syncthreads();
        sm[threadIdx.x] += t;
        __syncthreads();
    }
    if (threadIdx.x < nb) bsum[threadIdx.x] = sm[threadIdx.x] - v;
}

// add block offsets; mirror into cursor; set rowptr[Nn] = E
__global__ void scan3_kernel(int* __restrict__ rowptr, int* __restrict__ cursor,
                             const int* __restrict__ bsum, int Nn, int E) {
    int i = blockIdx.x * 256 + threadIdx.x;
    if (i < Nn) {
        int v = rowptr[i] + bsum[blockIdx.x];
        rowptr[i] = v;
        cursor[i] = v;
    }
    if (i == 0) rowptr[Nn] = E;
}

__global__ void fill_kernel(int* __restrict__ adj, int* __restrict__ cursor,
                            const int* __restrict__ ei, int E) {
    int e = blockIdx.x * blockDim.x + threadIdx.x;
    if (e < E) {
        int s = ei[e];
        int d = ei[(size_t)E + e];
        int p = atomicAdd(&cursor[d], 1);
        adj[p] = s;
    }
}

// ---------------------------------------------------------------------------
// gather: agg[n] = h[n] + sum_{s in adj[n]} h[s]
//   16 threads per node; indices batch-loaded and shuffled within half-warp.
// ---------------------------------------------------------------------------
__global__ void gather_kernel(float4* __restrict__ agg, const float4* __restrict__ h4,
                              const int* __restrict__ rowptr, const int* __restrict__ adj,
                              int Nn) {
    int tid  = blockIdx.x * blockDim.x + threadIdx.x;
    int lane = threadIdx.x & 31;
    int half = lane & 16;                         // 0 or 16
    unsigned hmask = half ? 0xffff0000u : 0x0000ffffu;
    int t = lane & 15;
    int n = tid >> 4;
    bool valid = (n < Nn);
    int n_cl = valid ? n : (Nn - 1);

    int start = rowptr[n_cl];
    int end   = rowptr[n_cl + 1];
    float4 acc = h4[(size_t)n_cl * 16 + t];       // the "+h" term

    for (int base = start; base < end; base += 16) {
        int rem = end - base;
        int cnt = rem < 16 ? rem : 16;
        int idx = (t < rem) ? adj[base + t] : 0;
        for (int j = 0; j < cnt; j++) {
            int s = __shfl_sync(hmask, idx, half + j);
            float4 v = h4[(size_t)s * 16 + t];
            acc.x += v.x; acc.y += v.y; acc.z += v.z; acc.w += v.w;
        }
    }
    if (valid) agg[(size_t)n * 16 + t] = acc;
}

// ---------------------------------------------------------------------------
// Register-blocked fused GEMM + sigmoid: Y = sigmoid(X @ W)
//   128 rows/block, 256 threads, 8 rows x 4 cols/thread, FMA2 over (k,k+1)
// ---------------------------------------------------------------------------
#define SXS 66
#define SWS 66
#define SW_FLOATS 4240
#define SX_FLOATS 8448
#define GEMM_SMEM_BYTES ((SW_FLOATS + SX_FLOATS) * 4)

__global__ __launch_bounds__(256, 2) void gemm_sig_kernel(
    float* __restrict__ Y, const float* __restrict__ X,
    const float* __restrict__ W, int Nn)
{
    extern __shared__ float sm[];
    float* sWT = sm;
    float* sX  = sm + SW_FLOATS;
    int tid  = threadIdx.x;
    int row0 = blockIdx.x * 128;

    const float4* W4 = (const float4*)W;
#pragma unroll
    for (int it = 0; it < 4; it++) {
        int idx = tid + it * 256;
        int k   = idx >> 4;
        int c4  = idx & 15;
        float4 v = W4[idx];
        int c = c4 * 4;
        sWT[(c + 0) * SWS + (((c + 0) >> 4) & 3) * 2 + k] = v.x;
        sWT[(c + 1) * SWS + (((c + 1) >> 4) & 3) * 2 + k] = v.y;
        sWT[(c + 2) * SWS + (((c + 2) >> 4) & 3) * 2 + k] = v.z;
        sWT[(c + 3) * SWS + (((c + 3) >> 4) & 3) * 2 + k] = v.w;
    }

    const float4* X4 = (const float4*)X;
#pragma unroll
    for (int it = 0; it < 8; it++) {
        int idx = tid + it * 256;
        int r   = idx >> 4;
        int k4  = idx & 15;
        int grow = row0 + r;
        float4 v = make_float4(0.f, 0.f, 0.f, 0.f);
        if (grow < Nn) v = X4[(size_t)grow * 16 + k4];
        float* dp = &sX[r * SXS + k4 * 4];
        dp[0] = v.x; dp[1] = v.y; dp[2] = v.z; dp[3] = v.w;
    }
    __syncthreads();

    int tr = tid >> 4;
    int tc = tid & 15;
    const float* xb = sX + tr * 8 * SXS;
    const float* wb = sWT + tc * 4 * SWS + ((tc >> 2) & 3) * 2;

    unsigned long long acc[4][8];
#pragma unroll
    for (int c = 0; c < 4; c++)
#pragma unroll
        for (int i = 0; i < 8; i++) acc[c][i] = 0ull;

#pragma unroll 2
    for (int k = 0; k < 64; k += 2) {
        unsigned long long xv[8], wv[4];
#pragma unroll
        for (int i = 0; i < 8; i++)
            xv[i] = *(const unsigned long long*)(xb + i * SXS + k);
#pragma unroll
        for (int c = 0; c < 4; c++)
            wv[c] = *(const unsigned long long*)(wb + c * SWS + k);
#pragma unroll
        for (int i = 0; i < 8; i++)
#pragma unroll
            for (int c = 0; c < 4; c++)
                asm("fma.rn.f32x2 %0, %1, %2, %0;"
                    : "+l"(acc[c][i]) : "l"(xv[i]), "l"(wv[c]));
    }

    int cbase = tc * 4;
#pragma unroll
    for (int i = 0; i < 8; i++) {
        int row = row0 + tr * 8 + i;
        if (row < Nn) {
            float o[4];
#pragma unroll
            for (int c = 0; c < 4; c++) {
                float lo, hi;
                asm("mov.b64 {%0, %1}, %2;" : "=f"(lo), "=f"(hi) : "l"(acc[c][i]));
                float v = lo + hi;
                o[c] = 1.0f / (1.0f + __expf(-v));
            }
            *(float4*)(Y + (size_t)row * 64 + cbase) = make_float4(o[0], o[1], o[2], o[3]);
        }
    }
}

// ---------------------------------------------------------------------------
// pool: xr[batch[n]] += h[n]
// ---------------------------------------------------------------------------
__global__ void pool_kernel(float4* __restrict__ xr, const float4* __restrict__ h,
                            const int* __restrict__ batch, int Nn) {
    int tid  = blockIdx.x * blockDim.x + threadIdx.x;
    int lane = threadIdx.x & 31;
    int n    = tid >> 4;
    int n_cl = min(n, Nn - 1);
    int g = 0;
    if ((lane & 15) == 0) g = batch[n_cl];
    g = __shfl_sync(0xffffffffu, g, lane & 16);
    int f4 = tid & 15;
    float4 v = h[(size_t)n_cl * 16 + f4];
    if (n < Nn) {
        float4* p = xr + (size_t)g * 16 + f4;
        asm volatile("red.global.add.v4.f32 [%0], {%1, %2, %3, %4};"
                     :: "l"(p), "f"(v.x), "f"(v.y), "f"(v.z), "f"(v.w)
                     : "memory");
    }
}

// ---------------------------------------------------------------------------
// head: logits = xr @ fc_w^T + fc_b ; out = log_softmax(logits)
// ---------------------------------------------------------------------------
__global__ void head_kernel(float* __restrict__ out, const float* __restrict__ xr,
                            const float* __restrict__ fc_w, const float* __restrict__ fc_b,
                            int C, int B) {
    int g = blockIdx.x * blockDim.x + threadIdx.x;
    if (g >= B) return;
    float xv[FEAT];
#pragma unroll
    for (int i = 0; i < FEAT; i++) xv[i] = xr[(size_t)g * FEAT + i];
    float lg[16];
    float m = -1e30f;
    for (int c = 0; c < C; c++) {
        float s = fc_b[c];
#pragma unroll
        for (int i = 0; i < FEAT; i++) s += xv[i] * fc_w[(size_t)c * FEAT + i];
        lg[c] = s;
        m = fmaxf(m, s);
    }
    float sum = 0.0f;
    for (int c = 0; c < C; c++) sum += expf(lg[c] - m);
    float lse = m + logf(sum);
    for (int c = 0; c < C; c++) out[(size_t)g * C + c] = lg[c] - lse;
}

// ---------------------------------------------------------------------------
extern "C" void kernel_launch(void* const* d_in, const int* in_sizes, int n_in,
                              void* d_out, int out_size) {
    const float* x     = (const float*)d_in[0];
    const int*   ei    = (const int*)d_in[1];    // int64 narrowed to int32 by harness
    const int*   batch = (const int*)d_in[2];
    const float* W1s   = (const float*)d_in[3];
    const float* W2s   = (const float*)d_in[4];
    const float* fc_w  = (const float*)d_in[5];
    const float* fc_b  = (const float*)d_in[6];

    int Nn = in_sizes[0] / FEAT;           // 100000
    int E  = in_sizes[1] / 2;              // 1600000
    int C  = in_sizes[6];                  // 10
    int L  = in_sizes[3] / (FEAT * FEAT);  // 4
    int B  = out_size / (C + FEAT);        // 128

    static int smem_set = 0;
    if (!smem_set) {
        cudaFuncSetAttribute(gemm_sig_kernel,
                             cudaFuncAttributeMaxDynamicSharedMemorySize,
                             GEMM_SMEM_BYTES);
        smem_set = 1;
    }

    float4 *bufA4, *bufB4;
    int *rowptr, *cursor, *adj, *bsum;
    cudaGetSymbolAddress((void**)&bufA4, g_bufA);
    cudaGetSymbolAddress((void**)&bufB4, g_bufB);
    cudaGetSymbolAddress((void**)&rowptr, g_rowptr);
    cudaGetSymbolAddress((void**)&cursor, g_cursor);
    cudaGetSymbolAddress((void**)&adj, g_adj);
    cudaGetSymbolAddress((void**)&bsum, g_bsum);
    float* A  = (float*)bufA4;
    float* Bv = (float*)bufB4;

    int nb        = (Nn + 255) / 256;          // scan blocks (391 <= 512)
    int eBlocks   = (E + 255) / 256;
    int nodeBlks  = (Nn * 16 + 255) / 256;
    int gemmBlks  = (Nn + 127) / 128;

    // ---- CSR build (once per launch) ----
    zero_int_kernel<<<nb, 256>>>(cursor, Nn);              // cursor = degree hist
    hist_kernel<<<eBlocks, 256>>>(cursor, ei, E);
    scan1_kernel<<<nb, 256>>>(cursor, rowptr, bsum, Nn);
    scan2_kernel<<<1, 512>>>(bsum, nb);
    scan3_kernel<<<nb, 256>>>(rowptr, cursor, bsum, Nn, E);
    fill_kernel<<<eBlocks, 256>>>(adj, cursor, ei, E);

    // ---- layers ----
    for (int l = 0; l < L; l++) {
        const float* h = (l == 0) ? x : Bv;
        gather_kernel<<<nodeBlks, 256>>>((float4*)A, (const float4*)h, rowptr, adj, Nn);
        gemm_sig_kernel<<<gemmBlks, 256, GEMM_SMEM_BYTES>>>(
            A, A, W1s + (size_t)l * FEAT * FEAT, Nn);
        gemm_sig_kernel<<<gemmBlks, 256, GEMM_SMEM_BYTES>>>(
            Bv, A, W2s + (size_t)l * FEAT * FEAT, Nn);
    }

    float* out = (float*)d_out;
    float* xr  = out + (size_t)B * C;

    zero_kernel<<<(out_size + 255) / 256, 256>>>(out, out_size);
    pool_kernel<<<nodeBlks, 256>>>((float4*)xr, (const float4*)Bv, batch, Nn);
    head_kernel<<<(B + 127) / 128, 128>>>(out, xr, fc_w, fc_b, C, B);
}

// round 6
// speedup vs baseline: 2.3161x; 1.0634x over previous
#include <cuda_runtime.h>

#define FEAT 64

// Scratch buffers (static __device__ — no allocation allowed).
#define NMAX 100000
#define EMAX 1600000
__device__ float4 g_bufA[(size_t)NMAX * (FEAT / 4)];
__device__ float4 g_bufB[(size_t)NMAX * (FEAT / 4)];
__device__ int    g_rowptr[NMAX + 1];
__device__ int    g_cursor[NMAX];      // doubles as degree histogram
__device__ int    g_adj[EMAX];
__device__ int    g_bsum[1024];

// ---------------------------------------------------------------------------
__global__ void zero_kernel(float* __restrict__ p, int n) {
    int i = blockIdx.x * blockDim.x + threadIdx.x;
    if (i < n) p[i] = 0.0f;
}
__global__ void zero_int_kernel(int* __restrict__ p, int n) {
    int i = blockIdx.x * blockDim.x + threadIdx.x;
    if (i < n) p[i] = 0;
}

// ---------------------------------------------------------------------------
// CSR build: histogram -> scan -> fill
// ---------------------------------------------------------------------------
__global__ void hist_kernel(int* __restrict__ deg, const int* __restrict__ ei, int E) {
    int e = blockIdx.x * blockDim.x + threadIdx.x;
    if (e < E) atomicAdd(&deg[ei[(size_t)E + e]], 1);
}

__global__ void scan1_kernel(const int* __restrict__ deg, int* __restrict__ rowptr,
                             int* __restrict__ bsum, int Nn) {
    __shared__ int sm[256];
    int i = blockIdx.x * 256 + threadIdx.x;
    int v = (i < Nn) ? deg[i] : 0;
    sm[threadIdx.x] = v;
    __syncthreads();
    for (int off = 1; off < 256; off <<= 1) {
        int t = (threadIdx.x >= off) ? sm[threadIdx.x - off] : 0;
        __syncthreads();
        sm[threadIdx.x] += t;
        __syncthreads();
    }
    if (i < Nn) rowptr[i] = sm[threadIdx.x] - v;
    if (threadIdx.x == 255) bsum[blockIdx.x] = sm[255];
}

__global__ void scan2_kernel(int* __restrict__ bsum, int nb) {
    __shared__ int sm[512];
    int v = (threadIdx.x < nb) ? bsum[threadIdx.x] : 0;
    sm[threadIdx.x] = v;
    __syncthreads();
    for (int off = 1; off < 512; off <<= 1) {
        int t = (threadIdx.x >= off) ? sm[threadIdx.x - off] : 0;
        __syncthreads();
        sm[threadIdx.x] += t;
        __syncthreads();
    }
    if (threadIdx.x < nb) bsum[threadIdx.x] = sm[threadIdx.x] - v;
}

__global__ void scan3_kernel(int* __restrict__ rowptr, int* __restrict__ cursor,
                             const int* __restrict__ bsum, int Nn, int E) {
    int i = blockIdx.x * 256 + threadIdx.x;
    if (i < Nn) {
        int v = rowptr[i] + bsum[blockIdx.x];
        rowptr[i] = v;
        cursor[i] = v;
    }
    if (i == 0) rowptr[Nn] = E;
}

__global__ void fill_kernel(int* __restrict__ adj, int* __restrict__ cursor,
                            const int* __restrict__ ei, int E) {
    int e = blockIdx.x * blockDim.x + threadIdx.x;
    if (e < E) {
        int s = ei[e];
        int d = ei[(size_t)E + e];
        int p = atomicAdd(&cursor[d], 1);
        adj[p] = s;
    }
}

// ---------------------------------------------------------------------------
// gather: agg[n] = h[n] + sum_{s in adj[n]} h[s]
//   16 threads/node; full-16 chunks fully unrolled for MLP.
// ---------------------------------------------------------------------------
__global__ void gather_kernel(float4* __restrict__ agg, const float4* __restrict__ h4,
                              const int* __restrict__ rowptr, const int* __restrict__ adj,
                              int Nn) {
    int tid  = blockIdx.x * blockDim.x + threadIdx.x;
    int lane = threadIdx.x & 31;
    int half = lane & 16;
    unsigned hmask = half ? 0xffff0000u : 0x0000ffffu;
    int t = lane & 15;
    int n = tid >> 4;
    bool valid = (n < Nn);
    int n_cl = valid ? n : (Nn - 1);

    int start = rowptr[n_cl];
    int end   = rowptr[n_cl + 1];
    float4 acc = h4[(size_t)n_cl * 16 + t];

    int base = start;
    for (; base + 16 <= end; base += 16) {          // full chunks, unrolled
        int idx = adj[base + t];
        float4 v[16];
#pragma unroll
        for (int j = 0; j < 16; j++) {
            int s = __shfl_sync(hmask, idx, half + j);
            v[j] = h4[(size_t)s * 16 + t];
        }
#pragma unroll
        for (int j = 0; j < 16; j++) {
            acc.x += v[j].x; acc.y += v[j].y; acc.z += v[j].z; acc.w += v[j].w;
        }
    }
    int rem = end - base;                            // tail
    if (rem > 0) {
        int idx = (t < rem) ? adj[base + t] : 0;
        for (int j = 0; j < rem; j++) {
            int s = __shfl_sync(hmask, idx, half + j);
            float4 v = h4[(size_t)s * 16 + t];
            acc.x += v.x; acc.y += v.y; acc.z += v.z; acc.w += v.w;
        }
    }
    if (valid) agg[(size_t)n * 16 + t] = acc;
}

// ---------------------------------------------------------------------------
// Fused layer MLP: Y = sigmoid(sigmoid(X @ W1) @ W2)
//   128 rows/block, 256 threads, 8 rows x 4 cols/thread, FMA2 over (k,k+1).
//   H1 stays in shared memory between the two GEMM stages.
//   smem: sW1T | sW2T | sX | sH1  (101.5 KB -> 2 blocks/SM, 32 warps/SM)
// ---------------------------------------------------------------------------
#define SXS 66
#define SWS 66
#define SW_FLOATS 4240
#define SX_FLOATS 8448
#define FUSED_SMEM_BYTES ((2 * SW_FLOATS + 2 * SX_FLOATS) * 4)

__device__ __forceinline__ void stage_wt(float* sWT, const float4* W4, int tid) {
#pragma unroll
    for (int it = 0; it < 4; it++) {
        int idx = tid + it * 256;
        int k   = idx >> 4;
        int c4  = idx & 15;
        float4 v = W4[idx];
        int c = c4 * 4;
        sWT[(c + 0) * SWS + (((c + 0) >> 4) & 3) * 2 + k] = v.x;
        sWT[(c + 1) * SWS + (((c + 1) >> 4) & 3) * 2 + k] = v.y;
        sWT[(c + 2) * SWS + (((c + 2) >> 4) & 3) * 2 + k] = v.z;
        sWT[(c + 3) * SWS + (((c + 3) >> 4) & 3) * 2 + k] = v.w;
    }
}

__device__ __forceinline__ void mlp_stage(const float* __restrict__ xb,
                                          const float* __restrict__ wb,
                                          float o[8][4]) {
    unsigned long long acc[4][8];
#pragma unroll
    for (int c = 0; c < 4; c++)
#pragma unroll
        for (int i = 0; i < 8; i++) acc[c][i] = 0ull;

#pragma unroll 2
    for (int k = 0; k < 64; k += 2) {
        unsigned long long xv[8], wv[4];
#pragma unroll
        for (int i = 0; i < 8; i++)
            xv[i] = *(const unsigned long long*)(xb + i * SXS + k);
#pragma unroll
        for (int c = 0; c < 4; c++)
            wv[c] = *(const unsigned long long*)(wb + c * SWS + k);
#pragma unroll
        for (int i = 0; i < 8; i++)
#pragma unroll
            for (int c = 0; c < 4; c++)
                asm("fma.rn.f32x2 %0, %1, %2, %0;"
                    : "+l"(acc[c][i]) : "l"(xv[i]), "l"(wv[c]));
    }
#pragma unroll
    for (int i = 0; i < 8; i++)
#pragma unroll
        for (int c = 0; c < 4; c++) {
            float lo, hi;
            asm("mov.b64 {%0, %1}, %2;" : "=f"(lo), "=f"(hi) : "l"(acc[c][i]));
            float v = lo + hi;
            o[i][c] = 1.0f / (1.0f + __expf(-v));
        }
}

__global__ __launch_bounds__(256, 2) void fused_layer_kernel(
    float* __restrict__ Y, const float* __restrict__ X,
    const float* __restrict__ W1, const float* __restrict__ W2, int Nn)
{
    extern __shared__ float sm[];
    float* sW1T = sm;
    float* sW2T = sm + SW_FLOATS;
    float* sX   = sm + 2 * SW_FLOATS;
    float* sH1  = sm + 2 * SW_FLOATS + SX_FLOATS;
    int tid  = threadIdx.x;
    int row0 = blockIdx.x * 128;

    stage_wt(sW1T, (const float4*)W1, tid);
    stage_wt(sW2T, (const float4*)W2, tid);

    const float4* X4 = (const float4*)X;
#pragma unroll
    for (int it = 0; it < 8; it++) {
        int idx = tid + it * 256;
        int r   = idx >> 4;
        int k4  = idx & 15;
        int grow = row0 + r;
        float4 v = make_float4(0.f, 0.f, 0.f, 0.f);
        if (grow < Nn) v = X4[(size_t)grow * 16 + k4];
        float* dp = &sX[r * SXS + k4 * 4];
        dp[0] = v.x; dp[1] = v.y; dp[2] = v.z; dp[3] = v.w;
    }
    __syncthreads();

    int tr = tid >> 4;
    int tc = tid & 15;
    int skew = ((tc >> 2) & 3) * 2;
    float o[8][4];

    // stage 1: H1 = sigmoid(X @ W1) -> shared
    mlp_stage(sX + tr * 8 * SXS, sW1T + tc * 4 * SWS + skew, o);
#pragma unroll
    for (int i = 0; i < 8; i++) {
        float* dp = &sH1[(tr * 8 + i) * SXS + tc * 4];
        dp[0] = o[i][0]; dp[1] = o[i][1]; dp[2] = o[i][2]; dp[3] = o[i][3];
    }
    __syncthreads();

    // stage 2: Y = sigmoid(H1 @ W2) -> global
    mlp_stage(sH1 + tr * 8 * SXS, sW2T + tc * 4 * SWS + skew, o);
    int cbase = tc * 4;
#pragma unroll
    for (int i = 0; i < 8; i++) {
        int row = row0 + tr * 8 + i;
        if (row < Nn)
            *(float4*)(Y + (size_t)row * 64 + cbase) =
                make_float4(o[i][0], o[i][1], o[i][2], o[i][3]);
    }
}

// ---------------------------------------------------------------------------
// pool: xr[batch[n]] += h[n]
// ---------------------------------------------------------------------------
__global__ void pool_kernel(float4* __restrict__ xr, const float4* __restrict__ h,
                            const int* __restrict__ batch, int Nn) {
    int tid  = blockIdx.x * blockDim.x + threadIdx.x;
    int lane = threadIdx.x & 31;
    int n    = tid >> 4;
    int n_cl = min(n, Nn - 1);
    int g = 0;
    if ((lane & 15) == 0) g = batch[n_cl];
    g = __shfl_sync(0xffffffffu, g, lane & 16);
    int f4 = tid & 15;
    float4 v = h[(size_t)n_cl * 16 + f4];
    if (n < Nn) {
        float4* p = xr + (size_t)g * 16 + f4;
        asm volatile("red.global.add.v4.f32 [%0], {%1, %2, %3, %4};"
                     :: "l"(p), "f"(v.x), "f"(v.y), "f"(v.z), "f"(v.w)
                     : "memory");
    }
}

// ---------------------------------------------------------------------------
// head: logits = xr @ fc_w^T + fc_b ; out = log_softmax(logits)
// ---------------------------------------------------------------------------
__global__ void head_kernel(float* __restrict__ out, const float* __restrict__ xr,
                            const float* __restrict__ fc_w, const float* __restrict__ fc_b,
                            int C, int B) {
    int g = blockIdx.x * blockDim.x + threadIdx.x;
    if (g >= B) return;
    float xv[FEAT];
#pragma unroll
    for (int i = 0; i < FEAT; i++) xv[i] = xr[(size_t)g * FEAT + i];
    float lg[16];
    float m = -1e30f;
    for (int c = 0; c < C; c++) {
        float s = fc_b[c];
#pragma unroll
        for (int i = 0; i < FEAT; i++) s += xv[i] * fc_w[(size_t)c * FEAT + i];
        lg[c] = s;
        m = fmaxf(m, s);
    }
    float sum = 0.0f;
    for (int c = 0; c < C; c++) sum += expf(lg[c] - m);
    float lse = m + logf(sum);
    for (int c = 0; c < C; c++) out[(size_t)g * C + c] = lg[c] - lse;
}

// ---------------------------------------------------------------------------
extern "C" void kernel_launch(void* const* d_in, const int* in_sizes, int n_in,
                              void* d_out, int out_size) {
    const float* x     = (const float*)d_in[0];
    const int*   ei    = (const int*)d_in[1];    // int64 narrowed to int32 by harness
    const int*   batch = (const int*)d_in[2];
    const float* W1s   = (const float*)d_in[3];
    const float* W2s   = (const float*)d_in[4];
    const float* fc_w  = (const float*)d_in[5];
    const float* fc_b  = (const float*)d_in[6];

    int Nn = in_sizes[0] / FEAT;           // 100000
    int E  = in_sizes[1] / 2;              // 1600000
    int C  = in_sizes[6];                  // 10
    int L  = in_sizes[3] / (FEAT * FEAT);  // 4
    int B  = out_size / (C + FEAT);        // 128

    static int smem_set = 0;
    if (!smem_set) {
        cudaFuncSetAttribute(fused_layer_kernel,
                             cudaFuncAttributeMaxDynamicSharedMemorySize,
                             FUSED_SMEM_BYTES);
        smem_set = 1;
    }

    float4 *bufA4, *bufB4;
    int *rowptr, *cursor, *adj, *bsum;
    cudaGetSymbolAddress((void**)&bufA4, g_bufA);
    cudaGetSymbolAddress((void**)&bufB4, g_bufB);
    cudaGetSymbolAddress((void**)&rowptr, g_rowptr);
    cudaGetSymbolAddress((void**)&cursor, g_cursor);
    cudaGetSymbolAddress((void**)&adj, g_adj);
    cudaGetSymbolAddress((void**)&bsum, g_bsum);
    float* A  = (float*)bufA4;
    float* Bv = (float*)bufB4;

    int nb        = (Nn + 255) / 256;
    int eBlocks   = (E + 255) / 256;
    int nodeBlks  = (Nn * 16 + 255) / 256;
    int gemmBlks  = (Nn + 127) / 128;

    // ---- CSR build (once per launch) ----
    zero_int_kernel<<<nb, 256>>>(cursor, Nn);
    hist_kernel<<<eBlocks, 256>>>(cursor, ei, E);
    scan1_kernel<<<nb, 256>>>(cursor, rowptr, bsum, Nn);
    scan2_kernel<<<1, 512>>>(bsum, nb);
    scan3_kernel<<<nb, 256>>>(rowptr, cursor, bsum, Nn, E);
    fill_kernel<<<eBlocks, 256>>>(adj, cursor, ei, E);

    // ---- layers ----
    for (int l = 0; l < L; l++) {
        const float* h = (l == 0) ? x : Bv;
        gather_kernel<<<nodeBlks, 256>>>((float4*)A, (const float4*)h, rowptr, adj, Nn);
        fused_layer_kernel<<<gemmBlks, 256, FUSED_SMEM_BYTES>>>(
            Bv, A, W1s + (size_t)l * FEAT * FEAT, W2s + (size_t)l * FEAT * FEAT, Nn);
    }

    float* out = (float*)d_out;
    float* xr  = out + (size_t)B * C;

    zero_kernel<<<(out_size + 255) / 256, 256>>>(out, out_size);
    pool_kernel<<<nodeBlks, 256>>>((float4*)xr, (const float4*)Bv, batch, Nn);
    head_kernel<<<(B + 127) / 128, 128>>>(out, xr, fc_w, fc_b, C, B);
}

// round 7
// speedup vs baseline: 2.5294x; 1.0921x over previous
#include <cuda_runtime.h>

#define FEAT 64

// Scratch buffers (static __device__ — no allocation allowed).
#define NMAX 100000
#define EMAX 1600000
__device__ float4 g_bufA[(size_t)NMAX * (FEAT / 4)];
__device__ float4 g_bufB[(size_t)NMAX * (FEAT / 4)];
__device__ int    g_rowptr[NMAX + 1];
__device__ int    g_cursor[NMAX];      // doubles as degree histogram
__device__ int    g_adj[EMAX];
__device__ int    g_bsum[1024];

// ---------------------------------------------------------------------------
__global__ void zero_kernel(float* __restrict__ p, int n) {
    int i = blockIdx.x * blockDim.x + threadIdx.x;
    if (i < n) p[i] = 0.0f;
}
__global__ void zero_int_kernel(int* __restrict__ p, int n) {
    int i = blockIdx.x * blockDim.x + threadIdx.x;
    if (i < n) p[i] = 0;
}

// ---------------------------------------------------------------------------
// CSR build: histogram -> scan -> fill
// ---------------------------------------------------------------------------
__global__ void hist_kernel(int* __restrict__ deg, const int* __restrict__ ei, int E) {
    int e = blockIdx.x * blockDim.x + threadIdx.x;
    if (e < E) atomicAdd(&deg[ei[(size_t)E + e]], 1);
}

__global__ void scan1_kernel(const int* __restrict__ deg, int* __restrict__ rowptr,
                             int* __restrict__ bsum, int Nn) {
    __shared__ int sm[256];
    int i = blockIdx.x * 256 + threadIdx.x;
    int v = (i < Nn) ? deg[i] : 0;
    sm[threadIdx.x] = v;
    __syncthreads();
    for (int off = 1; off < 256; off <<= 1) {
        int t = (threadIdx.x >= off) ? sm[threadIdx.x - off] : 0;
        __syncthreads();
        sm[threadIdx.x] += t;
        __syncthreads();
    }
    if (i < Nn) rowptr[i] = sm[threadIdx.x] - v;
    if (threadIdx.x == 255) bsum[blockIdx.x] = sm[255];
}

__global__ void scan2_kernel(int* __restrict__ bsum, int nb) {
    __shared__ int sm[512];
    int v = (threadIdx.x < nb) ? bsum[threadIdx.x] : 0;
    sm[threadIdx.x] = v;
    __syncthreads();
    for (int off = 1; off < 512; off <<= 1) {
        int t = (threadIdx.x >= off) ? sm[threadIdx.x - off] : 0;
        __syncthreads();
        sm[threadIdx.x] += t;
        __syncthreads();
    }
    if (threadIdx.x < nb) bsum[threadIdx.x] = sm[threadIdx.x] - v;
}

__global__ void scan3_kernel(int* __restrict__ rowptr, int* __restrict__ cursor,
                             const int* __restrict__ bsum, int Nn, int E) {
    int i = blockIdx.x * 256 + threadIdx.x;
    if (i < Nn) {
        int v = rowptr[i] + bsum[blockIdx.x];
        rowptr[i] = v;
        cursor[i] = v;
    }
    if (i == 0) rowptr[Nn] = E;
}

__global__ void fill_kernel(int* __restrict__ adj, int* __restrict__ cursor,
                            const int* __restrict__ ei, int E) {
    int e = blockIdx.x * blockDim.x + threadIdx.x;
    if (e < E) {
        int s = ei[e];
        int d = ei[(size_t)E + e];
        int p = atomicAdd(&cursor[d], 1);
        adj[p] = s;
    }
}

// ---------------------------------------------------------------------------
// Fused GIN layer: Y = sigmoid(sigmoid((h + sum_neigh h) @ W1) @ W2)
//   512 threads/block, 128 rows/block.
//   Phase 0: gather (half-warp per node) -> sX
//   Phase 1: H1 = sigmoid(sX @ W1) -> back into sX (aliased)
//   Phase 2: Y  = sigmoid(sX @ W2) -> global
//   smem = sW1T + sW2T + sX = 67.7 KB -> 2 blocks/SM, 32 warps/SM.
// ---------------------------------------------------------------------------
#define SXS 66
#define SWS 66
#define SW_FLOATS 4240
#define SX_FLOATS 8448
#define LAYER_SMEM_BYTES ((2 * SW_FLOATS + SX_FLOATS) * 4)

__device__ __forceinline__ void stage_wt512(float* sWT, const float4* W4, int tid) {
#pragma unroll
    for (int it = 0; it < 2; it++) {
        int idx = tid + it * 512;      // 0..1023
        int k   = idx >> 4;
        int c4  = idx & 15;
        float4 v = W4[idx];
        int c = c4 * 4;
        sWT[(c + 0) * SWS + (((c + 0) >> 4) & 3) * 2 + k] = v.x;
        sWT[(c + 1) * SWS + (((c + 1) >> 4) & 3) * 2 + k] = v.y;
        sWT[(c + 2) * SWS + (((c + 2) >> 4) & 3) * 2 + k] = v.z;
        sWT[(c + 3) * SWS + (((c + 3) >> 4) & 3) * 2 + k] = v.w;
    }
}

// 4 rows x 4 cols per thread, FMA2 paired over (k, k+1)
__device__ __forceinline__ void mlp4(const float* __restrict__ xb,
                                     const float* __restrict__ wb,
                                     float o[4][4]) {
    unsigned long long acc[4][4];
#pragma unroll
    for (int c = 0; c < 4; c++)
#pragma unroll
        for (int i = 0; i < 4; i++) acc[c][i] = 0ull;

#pragma unroll 4
    for (int k = 0; k < 64; k += 2) {
        unsigned long long xv[4], wv[4];
#pragma unroll
        for (int i = 0; i < 4; i++)
            xv[i] = *(const unsigned long long*)(xb + i * SXS + k);
#pragma unroll
        for (int c = 0; c < 4; c++)
            wv[c] = *(const unsigned long long*)(wb + c * SWS + k);
#pragma unroll
        for (int i = 0; i < 4; i++)
#pragma unroll
            for (int c = 0; c < 4; c++)
                asm("fma.rn.f32x2 %0, %1, %2, %0;"
                    : "+l"(acc[c][i]) : "l"(xv[i]), "l"(wv[c]));
    }
#pragma unroll
    for (int i = 0; i < 4; i++)
#pragma unroll
        for (int c = 0; c < 4; c++) {
            float lo, hi;
            asm("mov.b64 {%0, %1}, %2;" : "=f"(lo), "=f"(hi) : "l"(acc[c][i]));
            float v = lo + hi;
            o[i][c] = 1.0f / (1.0f + __expf(-v));
        }
}

__global__ __launch_bounds__(512, 2) void layer_kernel(
    float* __restrict__ Y, const float* __restrict__ H,
    const int* __restrict__ rowptr, const int* __restrict__ adj,
    const float* __restrict__ W1, const float* __restrict__ W2, int Nn)
{
    extern __shared__ float sm[];
    float* sW1T = sm;
    float* sW2T = sm + SW_FLOATS;
    float* sX   = sm + 2 * SW_FLOATS;
    int tid  = threadIdx.x;
    int row0 = blockIdx.x * 128;

    stage_wt512(sW1T, (const float4*)W1, tid);
    stage_wt512(sW2T, (const float4*)W2, tid);

    // ---- phase 0: gather 128 rows (half-warp per node, 32 nodes/pass) ----
    {
        int lane = tid & 31;
        int half = lane & 16;
        unsigned hmask = half ? 0xffff0000u : 0x0000ffffu;
        int t  = lane & 15;
        int hw = tid >> 4;               // 0..31
        const float4* H4 = (const float4*)H;
#pragma unroll
        for (int pass = 0; pass < 4; pass++) {
            int r = pass * 32 + hw;      // local row 0..127
            int n = row0 + r;
            bool valid = (n < Nn);
            int n_cl = valid ? n : (Nn - 1);
            int start = rowptr[n_cl];
            int end   = rowptr[n_cl + 1];
            float4 acc = H4[(size_t)n_cl * 16 + t];
            int base = start;
            for (; base + 16 <= end; base += 16) {
                int idx = adj[base + t];
                float4 v[8];
#pragma unroll
                for (int j = 0; j < 8; j++) {
                    int s = __shfl_sync(hmask, idx, half + j);
                    v[j] = H4[(size_t)s * 16 + t];
                }
#pragma unroll
                for (int j = 0; j < 8; j++) {
                    acc.x += v[j].x; acc.y += v[j].y; acc.z += v[j].z; acc.w += v[j].w;
                }
#pragma unroll
                for (int j = 0; j < 8; j++) {
                    int s = __shfl_sync(hmask, idx, half + 8 + j);
                    v[j] = H4[(size_t)s * 16 + t];
                }
#pragma unroll
                for (int j = 0; j < 8; j++) {
                    acc.x += v[j].x; acc.y += v[j].y; acc.z += v[j].z; acc.w += v[j].w;
                }
            }
            int rem = end - base;
            if (rem > 0) {
                int idx = (t < rem) ? adj[base + t] : 0;
                for (int j = 0; j < rem; j++) {
                    int s = __shfl_sync(hmask, idx, half + j);
                    float4 v = H4[(size_t)s * 16 + t];
                    acc.x += v.x; acc.y += v.y; acc.z += v.z; acc.w += v.w;
                }
            }
            float* dp = &sX[r * SXS + t * 4];
            dp[0] = acc.x; dp[1] = acc.y; dp[2] = acc.z; dp[3] = acc.w;
        }
    }
    __syncthreads();

    int tr = tid >> 4;      // 0..31 -> rows tr*4 .. tr*4+3
    int tc = tid & 15;      // 0..15 -> cols tc*4 .. tc*4+3
    int skew = ((tc >> 2) & 3) * 2;
    float o[4][4];

    // ---- phase 1: H1 = sigmoid(X @ W1), written back into sX ----
    mlp4(sX + tr * 4 * SXS, sW1T + tc * 4 * SWS + skew, o);
    __syncthreads();        // all reads of sX complete
#pragma unroll
    for (int i = 0; i < 4; i++) {
        float* dp = &sX[(tr * 4 + i) * SXS + tc * 4];
        dp[0] = o[i][0]; dp[1] = o[i][1]; dp[2] = o[i][2]; dp[3] = o[i][3];
    }
    __syncthreads();

    // ---- phase 2: Y = sigmoid(H1 @ W2) -> global ----
    mlp4(sX + tr * 4 * SXS, sW2T + tc * 4 * SWS + skew, o);
    int cbase = tc * 4;
#pragma unroll
    for (int i = 0; i < 4; i++) {
        int row = row0 + tr * 4 + i;
        if (row < Nn)
            *(float4*)(Y + (size_t)row * 64 + cbase) =
                make_float4(o[i][0], o[i][1], o[i][2], o[i][3]);
    }
}

// ---------------------------------------------------------------------------
// pool: xr[batch[n]] += h[n]
// ---------------------------------------------------------------------------
__global__ void pool_kernel(float4* __restrict__ xr, const float4* __restrict__ h,
                            const int* __restrict__ batch, int Nn) {
    int tid  = blockIdx.x * blockDim.x + threadIdx.x;
    int lane = threadIdx.x & 31;
    int n    = tid >> 4;
    int n_cl = min(n, Nn - 1);
    int g = 0;
    if ((lane & 15) == 0) g = batch[n_cl];
    g = __shfl_sync(0xffffffffu, g, lane & 16);
    int f4 = tid & 15;
    float4 v = h[(size_t)n_cl * 16 + f4];
    if (n < Nn) {
        float4* p = xr + (size_t)g * 16 + f4;
        asm volatile("red.global.add.v4.f32 [%0], {%1, %2, %3, %4};"
                     :: "l"(p), "f"(v.x), "f"(v.y), "f"(v.z), "f"(v.w)
                     : "memory");
    }
}

// ---------------------------------------------------------------------------
// head: logits = xr @ fc_w^T + fc_b ; out = log_softmax(logits)
// ---------------------------------------------------------------------------
__global__ void head_kernel(float* __restrict__ out, const float* __restrict__ xr,
                            const float* __restrict__ fc_w, const float* __restrict__ fc_b,
                            int C, int B) {
    int g = blockIdx.x * blockDim.x + threadIdx.x;
    if (g >= B) return;
    float xv[FEAT];
#pragma unroll
    for (int i = 0; i < FEAT; i++) xv[i] = xr[(size_t)g * FEAT + i];
    float lg[16];
    float m = -1e30f;
    for (int c = 0; c < C; c++) {
        float s = fc_b[c];
#pragma unroll
        for (int i = 0; i < FEAT; i++) s += xv[i] * fc_w[(size_t)c * FEAT + i];
        lg[c] = s;
        m = fmaxf(m, s);
    }
    float sum = 0.0f;
    for (int c = 0; c < C; c++) sum += expf(lg[c] - m);
    float lse = m + logf(sum);
    for (int c = 0; c < C; c++) out[(size_t)g * C + c] = lg[c] - lse;
}

// ---------------------------------------------------------------------------
extern "C" void kernel_launch(void* const* d_in, const int* in_sizes, int n_in,
                              void* d_out, int out_size) {
    const float* x     = (const float*)d_in[0];
    const int*   ei    = (const int*)d_in[1];    // int64 narrowed to int32 by harness
    const int*   batch = (const int*)d_in[2];
    const float* W1s   = (const float*)d_in[3];
    const float* W2s   = (const float*)d_in[4];
    const float* fc_w  = (const float*)d_in[5];
    const float* fc_b  = (const float*)d_in[6];

    int Nn = in_sizes[0] / FEAT;           // 100000
    int E  = in_sizes[1] / 2;              // 1600000
    int C  = in_sizes[6];                  // 10
    int L  = in_sizes[3] / (FEAT * FEAT);  // 4
    int B  = out_size / (C + FEAT);        // 128

    static int smem_set = 0;
    if (!smem_set) {
        cudaFuncSetAttribute(layer_kernel,
                             cudaFuncAttributeMaxDynamicSharedMemorySize,
                             LAYER_SMEM_BYTES);
        smem_set = 1;
    }

    float4 *bufA4, *bufB4;
    int *rowptr, *cursor, *adj, *bsum;
    cudaGetSymbolAddress((void**)&bufA4, g_bufA);
    cudaGetSymbolAddress((void**)&bufB4, g_bufB);
    cudaGetSymbolAddress((void**)&rowptr, g_rowptr);
    cudaGetSymbolAddress((void**)&cursor, g_cursor);
    cudaGetSymbolAddress((void**)&adj, g_adj);
    cudaGetSymbolAddress((void**)&bsum, g_bsum);
    float* A  = (float*)bufA4;
    float* Bv = (float*)bufB4;

    int nb        = (Nn + 255) / 256;
    int eBlocks   = (E + 255) / 256;
    int nodeBlks  = (Nn * 16 + 255) / 256;
    int layerBlks = (Nn + 127) / 128;

    // ---- CSR build (once per launch) ----
    zero_int_kernel<<<nb, 256>>>(cursor, Nn);
    hist_kernel<<<eBlocks, 256>>>(cursor, ei, E);
    scan1_kernel<<<nb, 256>>>(cursor, rowptr, bsum, Nn);
    scan2_kernel<<<1, 512>>>(bsum, nb);
    scan3_kernel<<<nb, 256>>>(rowptr, cursor, bsum, Nn, E);
    fill_kernel<<<eBlocks, 256>>>(adj, cursor, ei, E);

    // ---- layers (ping-pong; layer reads H anywhere, writes the other buf) ----
    const float* H = x;
    float* Y = A;
    for (int l = 0; l < L; l++) {
        layer_kernel<<<layerBlks, 512, LAYER_SMEM_BYTES>>>(
            Y, H, rowptr, adj,
            W1s + (size_t)l * FEAT * FEAT, W2s + (size_t)l * FEAT * FEAT, Nn);
        H = Y;
        Y = (Y == A) ? Bv : A;
    }

    float* out = (float*)d_out;
    float* xr  = out + (size_t)B * C;

    zero_kernel<<<(out_size + 255) / 256, 256>>>(out, out_size);
    pool_kernel<<<nodeBlks, 256>>>((float4*)xr, (const float4*)H, batch, Nn);
    head_kernel<<<(B + 127) / 128, 128>>>(out, xr, fc_w, fc_b, C, B);
}

// round 8
// speedup vs baseline: 2.6430x; 1.0449x over previous
#include <cuda_runtime.h>

#define FEAT 64

// Scratch buffers (static __device__ — no allocation allowed).
#define NMAX 100000
#define EMAX 1600000
__device__ float4 g_bufA[(size_t)NMAX * (FEAT / 4)];
__device__ float4 g_bufB[(size_t)NMAX * (FEAT / 4)];
__device__ int    g_rowptr[NMAX + 1];
__device__ int    g_cursor[NMAX];      // doubles as degree histogram
__device__ int    g_adj[EMAX];
__device__ int    g_bsum[1024];

// ---------------------------------------------------------------------------
__global__ void zero_kernel(float* __restrict__ p, int n) {
    int i = blockIdx.x * blockDim.x + threadIdx.x;
    if (i < n) p[i] = 0.0f;
}
__global__ void zero_int_kernel(int* __restrict__ p, int n) {
    int i = blockIdx.x * blockDim.x + threadIdx.x;
    if (i < n) p[i] = 0;
}

// ---------------------------------------------------------------------------
// CSR build: histogram -> scan -> fill
// ---------------------------------------------------------------------------
__global__ void hist_kernel(int* __restrict__ deg, const int* __restrict__ ei, int E) {
    int e = blockIdx.x * blockDim.x + threadIdx.x;
    if (e < E) atomicAdd(&deg[ei[(size_t)E + e]], 1);
}

__global__ void scan1_kernel(const int* __restrict__ deg, int* __restrict__ rowptr,
                             int* __restrict__ bsum, int Nn) {
    __shared__ int sm[256];
    int i = blockIdx.x * 256 + threadIdx.x;
    int v = (i < Nn) ? deg[i] : 0;
    sm[threadIdx.x] = v;
    __syncthreads();
    for (int off = 1; off < 256; off <<= 1) {
        int t = (threadIdx.x >= off) ? sm[threadIdx.x - off] : 0;
        __syncthreads();
        sm[threadIdx.x] += t;
        __syncthreads();
    }
    if (i < Nn) rowptr[i] = sm[threadIdx.x] - v;
    if (threadIdx.x == 255) bsum[blockIdx.x] = sm[255];
}

// add block offsets (each block reduces bsum[0..bid) itself); mirror into
// cursor; set rowptr[Nn] = E.  Replaces the old separate scan2 pass.
__global__ void scan3_kernel(int* __restrict__ rowptr, int* __restrict__ cursor,
                             const int* __restrict__ bsum, int Nn, int E) {
    __shared__ int sred[256];
    int t = threadIdx.x;
    int partial = 0;
    for (int j = t; j < blockIdx.x; j += 256) partial += bsum[j];
    sred[t] = partial;
    __syncthreads();
    for (int off = 128; off > 0; off >>= 1) {
        if (t < off) sred[t] += sred[t + off];
        __syncthreads();
    }
    int blockOff = sred[0];
    int i = blockIdx.x * 256 + t;
    if (i < Nn) {
        int v = rowptr[i] + blockOff;
        rowptr[i] = v;
        cursor[i] = v;
    }
    if (i == 0) rowptr[Nn] = E;
}

__global__ void fill_kernel(int* __restrict__ adj, int* __restrict__ cursor,
                            const int* __restrict__ ei, int E) {
    int e = blockIdx.x * blockDim.x + threadIdx.x;
    if (e < E) {
        int s = ei[e];
        int d = ei[(size_t)E + e];
        int p = atomicAdd(&cursor[d], 1);
        adj[p] = s;
    }
}

// ---------------------------------------------------------------------------
// Fused GIN layer: Y = sigmoid(sigmoid((h + sum_neigh h) @ W1) @ W2)
//   512 threads/block, 128 rows/block.
//   Phase 0: gather (half-warp per node) -> sX
//   Phase 1: H1 = sigmoid(sX @ W1) -> back into sX (aliased)
//   Phase 2: Y  = sigmoid(sX @ W2) -> global  (or RED into xr[batch] if xr!=0)
// ---------------------------------------------------------------------------
#define SXS 66
#define SWS 66
#define SW_FLOATS 4240
#define SX_FLOATS 8448
#define LAYER_SMEM_BYTES ((2 * SW_FLOATS + SX_FLOATS) * 4)

__device__ __forceinline__ void stage_wt512(float* sWT, const float4* W4, int tid) {
#pragma unroll
    for (int it = 0; it < 2; it++) {
        int idx = tid + it * 512;      // 0..1023
        int k   = idx >> 4;
        int c4  = idx & 15;
        float4 v = W4[idx];
        int c = c4 * 4;
        sWT[(c + 0) * SWS + (((c + 0) >> 4) & 3) * 2 + k] = v.x;
        sWT[(c + 1) * SWS + (((c + 1) >> 4) & 3) * 2 + k] = v.y;
        sWT[(c + 2) * SWS + (((c + 2) >> 4) & 3) * 2 + k] = v.z;
        sWT[(c + 3) * SWS + (((c + 3) >> 4) & 3) * 2 + k] = v.w;
    }
}

// 4 rows x 4 cols per thread, FMA2 paired over (k, k+1)
__device__ __forceinline__ void mlp4(const float* __restrict__ xb,
                                     const float* __restrict__ wb,
                                     float o[4][4]) {
    unsigned long long acc[4][4];
#pragma unroll
    for (int c = 0; c < 4; c++)
#pragma unroll
        for (int i = 0; i < 4; i++) acc[c][i] = 0ull;

#pragma unroll 4
    for (int k = 0; k < 64; k += 2) {
        unsigned long long xv[4], wv[4];
#pragma unroll
        for (int i = 0; i < 4; i++)
            xv[i] = *(const unsigned long long*)(xb + i * SXS + k);
#pragma unroll
        for (int c = 0; c < 4; c++)
            wv[c] = *(const unsigned long long*)(wb + c * SWS + k);
#pragma unroll
        for (int i = 0; i < 4; i++)
#pragma unroll
            for (int c = 0; c < 4; c++)
                asm("fma.rn.f32x2 %0, %1, %2, %0;"
                    : "+l"(acc[c][i]) : "l"(xv[i]), "l"(wv[c]));
    }
#pragma unroll
    for (int i = 0; i < 4; i++)
#pragma unroll
        for (int c = 0; c < 4; c++) {
            float lo, hi;
            asm("mov.b64 {%0, %1}, %2;" : "=f"(lo), "=f"(hi) : "l"(acc[c][i]));
            float v = lo + hi;
            o[i][c] = 1.0f / (1.0f + __expf(-v));
        }
}

__global__ __launch_bounds__(512, 2) void layer_kernel(
    float* __restrict__ Y, const float* __restrict__ H,
    const int* __restrict__ rowptr, const int* __restrict__ adj,
    const float* __restrict__ W1, const float* __restrict__ W2,
    float* __restrict__ xr, const int* __restrict__ batch, int Nn)
{
    extern __shared__ float sm[];
    float* sW1T = sm;
    float* sW2T = sm + SW_FLOATS;
    float* sX   = sm + 2 * SW_FLOATS;
    int tid  = threadIdx.x;
    int row0 = blockIdx.x * 128;

    stage_wt512(sW1T, (const float4*)W1, tid);
    stage_wt512(sW2T, (const float4*)W2, tid);

    // ---- phase 0: gather 128 rows (half-warp per node, 32 nodes/pass) ----
    {
        int lane = tid & 31;
        int half = lane & 16;
        unsigned hmask = half ? 0xffff0000u : 0x0000ffffu;
        int t  = lane & 15;
        int hw = tid >> 4;               // 0..31
        const float4* H4 = (const float4*)H;
#pragma unroll
        for (int pass = 0; pass < 4; pass++) {
            int r = pass * 32 + hw;      // local row 0..127
            int n = row0 + r;
            bool valid = (n < Nn);
            int n_cl = valid ? n : (Nn - 1);
            int start = rowptr[n_cl];
            int end   = rowptr[n_cl + 1];
            float4 acc = H4[(size_t)n_cl * 16 + t];
            int base = start;
            for (; base + 16 <= end; base += 16) {
                int idx = adj[base + t];
                float4 v[8];
#pragma unroll
                for (int j = 0; j < 8; j++) {
                    int s = __shfl_sync(hmask, idx, half + j);
                    v[j] = H4[(size_t)s * 16 + t];
                }
#pragma unroll
                for (int j = 0; j < 8; j++) {
                    acc.x += v[j].x; acc.y += v[j].y; acc.z += v[j].z; acc.w += v[j].w;
                }
#pragma unroll
                for (int j = 0; j < 8; j++) {
                    int s = __shfl_sync(hmask, idx, half + 8 + j);
                    v[j] = H4[(size_t)s * 16 + t];
                }
#pragma unroll
                for (int j = 0; j < 8; j++) {
                    acc.x += v[j].x; acc.y += v[j].y; acc.z += v[j].z; acc.w += v[j].w;
                }
            }
            int rem = end - base;
            if (rem > 0) {
                int idx = (t < rem) ? adj[base + t] : 0;
                for (int j = 0; j < rem; j++) {
                    int s = __shfl_sync(hmask, idx, half + j);
                    float4 v = H4[(size_t)s * 16 + t];
                    acc.x += v.x; acc.y += v.y; acc.z += v.z; acc.w += v.w;
                }
            }
            float* dp = &sX[r * SXS + t * 4];
            dp[0] = acc.x; dp[1] = acc.y; dp[2] = acc.z; dp[3] = acc.w;
        }
    }
    __syncthreads();

    int tr = tid >> 4;      // 0..31 -> rows tr*4 .. tr*4+3
    int tc = tid & 15;      // 0..15 -> cols tc*4 .. tc*4+3
    int skew = ((tc >> 2) & 3) * 2;
    float o[4][4];

    // ---- phase 1: H1 = sigmoid(X @ W1), written back into sX ----
    mlp4(sX + tr * 4 * SXS, sW1T + tc * 4 * SWS + skew, o);
    __syncthreads();        // all reads of sX complete
#pragma unroll
    for (int i = 0; i < 4; i++) {
        float* dp = &sX[(tr * 4 + i) * SXS + tc * 4];
        dp[0] = o[i][0]; dp[1] = o[i][1]; dp[2] = o[i][2]; dp[3] = o[i][3];
    }
    __syncthreads();

    // ---- phase 2: Y = sigmoid(H1 @ W2) ----
    mlp4(sX + tr * 4 * SXS, sW2T + tc * 4 * SWS + skew, o);
    int cbase = tc * 4;
    if (xr == nullptr) {
#pragma unroll
        for (int i = 0; i < 4; i++) {
            int row = row0 + tr * 4 + i;
            if (row < Nn)
                *(float4*)(Y + (size_t)row * 64 + cbase) =
                    make_float4(o[i][0], o[i][1], o[i][2], o[i][3]);
        }
    } else {
        // final layer: pool fused — RED into xr[batch[row]]
#pragma unroll
        for (int i = 0; i < 4; i++) {
            int row = row0 + tr * 4 + i;
            if (row < Nn) {
                int g = batch[row];
                float* p = xr + (size_t)g * 64 + cbase;
                asm volatile("red.global.add.v4.f32 [%0], {%1, %2, %3, %4};"
                             :: "l"(p), "f"(o[i][0]), "f"(o[i][1]),
                                "f"(o[i][2]), "f"(o[i][3])
                             : "memory");
            }
        }
    }
}

// ---------------------------------------------------------------------------
// head: logits = xr @ fc_w^T + fc_b ; out = log_softmax(logits)
// ---------------------------------------------------------------------------
__global__ void head_kernel(float* __restrict__ out, const float* __restrict__ xr,
                            const float* __restrict__ fc_w, const float* __restrict__ fc_b,
                            int C, int B) {
    int g = blockIdx.x * blockDim.x + threadIdx.x;
    if (g >= B) return;
    float xv[FEAT];
#pragma unroll
    for (int i = 0; i < FEAT; i++) xv[i] = xr[(size_t)g * FEAT + i];
    float lg[16];
    float m = -1e30f;
    for (int c = 0; c < C; c++) {
        float s = fc_b[c];
#pragma unroll
        for (int i = 0; i < FEAT; i++) s += xv[i] * fc_w[(size_t)c * FEAT + i];
        lg[c] = s;
        m = fmaxf(m, s);
    }
    float sum = 0.0f;
    for (int c = 0; c < C; c++) sum += expf(lg[c] - m);
    float lse = m + logf(sum);
    for (int c = 0; c < C; c++) out[(size_t)g * C + c] = lg[c] - lse;
}

// ---------------------------------------------------------------------------
extern "C" void kernel_launch(void* const* d_in, const int* in_sizes, int n_in,
                              void* d_out, int out_size) {
    const float* x     = (const float*)d_in[0];
    const int*   ei    = (const int*)d_in[1];    // int64 narrowed to int32 by harness
    const int*   batch = (const int*)d_in[2];
    const float* W1s   = (const float*)d_in[3];
    const float* W2s   = (const float*)d_in[4];
    const float* fc_w  = (const float*)d_in[5];
    const float* fc_b  = (const float*)d_in[6];

    int Nn = in_sizes[0] / FEAT;           // 100000
    int E  = in_sizes[1] / 2;              // 1600000
    int C  = in_sizes[6];                  // 10
    int L  = in_sizes[3] / (FEAT * FEAT);  // 4
    int B  = out_size / (C + FEAT);        // 128

    static int smem_set = 0;
    if (!smem_set) {
        cudaFuncSetAttribute(layer_kernel,
                             cudaFuncAttributeMaxDynamicSharedMemorySize,
                             LAYER_SMEM_BYTES);
        smem_set = 1;
    }

    float4 *bufA4, *bufB4;
    int *rowptr, *cursor, *adj, *bsum;
    cudaGetSymbolAddress((void**)&bufA4, g_bufA);
    cudaGetSymbolAddress((void**)&bufB4, g_bufB);
    cudaGetSymbolAddress((void**)&rowptr, g_rowptr);
    cudaGetSymbolAddress((void**)&cursor, g_cursor);
    cudaGetSymbolAddress((void**)&adj, g_adj);
    cudaGetSymbolAddress((void**)&bsum, g_bsum);
    float* A  = (float*)bufA4;
    float* Bv = (float*)bufB4;

    int nb        = (Nn + 255) / 256;
    int eBlocks   = (E + 255) / 256;
    int layerBlks = (Nn + 127) / 128;

    float* out = (float*)d_out;
    float* xr  = out + (size_t)B * C;

    // ---- CSR build (once per launch) ----
    zero_int_kernel<<<nb, 256>>>(cursor, Nn);
    hist_kernel<<<eBlocks, 256>>>(cursor, ei, E);
    scan1_kernel<<<nb, 256>>>(cursor, rowptr, bsum, Nn);
    scan3_kernel<<<nb, 256>>>(rowptr, cursor, bsum, Nn, E);
    fill_kernel<<<eBlocks, 256>>>(adj, cursor, ei, E);

    // zero output (xr is RED target of the final fused layer)
    zero_kernel<<<(out_size + 255) / 256, 256>>>(out, out_size);

    // ---- layers (ping-pong; final layer REDs into xr instead of writing H) ----
    const float* H = x;
    float* Y = A;
    for (int l = 0; l < L; l++) {
        bool last = (l == L - 1);
        layer_kernel<<<layerBlks, 512, LAYER_SMEM_BYTES>>>(
            Y, H, rowptr, adj,
            W1s + (size_t)l * FEAT * FEAT, W2s + (size_t)l * FEAT * FEAT,
            last ? xr : nullptr, batch, Nn);
        H = Y;
        Y = (Y == A) ? Bv : A;
    }

    head_kernel<<<(B + 127) / 128, 128>>>(out, xr, fc_w, fc_b, C, B);
}